// round 5
// baseline (speedup 1.0000x reference)
#include <cuda_runtime.h>
#include <cuda_bf16.h>

#define BN 8
#define MO 12
#define DD 512
#define NO 37
#define NA 6
#define NT 3
#define EM 128
#define NAA 100
#define NC 300
#define KK 72
#define PP 5112            // KK*(KK-1)
#define FD 1536
#define HF 768
#define TPB 512
#define PCH 10             // ceil(PP/512)
#define PAIRB (BN*PCH)     // 80 pair blocks
#define NDOT (NO+NA+6)     // 49 dots per head block

// phase-1 grid layout
#define HEADB (BN*MO)              // 96
#define PPB   8
#define POOLB (BN*PPB)             // 64
#define TABB  4
#define GRID  (HEADB + POOLB + TABB + 1)   // 165
#define PRODB (HEADB + TABB + 1)           // 101 producers pair blocks wait on
#define DONEB (POOLB + PAIRB)              // 144 blocks finalize waits on
#define FSL   (BN*NC/PAIRB)                // 30 finalize elements per pair block

// output layout (flattened, tuple order)
#define OFF_FINAL 0
#define OFF_PL    (BN*NC)
#define OFF_TT    (OFF_PL + BN*PP*NT)
#define OFF_ACT   (OFF_TT + BN*PP*NT)
#define OFF_OBJ   (OFF_ACT + BN*MO*NA)

// ---------------- device scratch ----------------
__device__ int      g_sel6[BN*MO];
__device__ int      g_aaidx[BN*KK];
__device__ int      g_objidx[BN*MO];
__device__ float    g_inpdot[BN*MO*6];
__device__ float    g_objtab[NO*6];
__device__ float    g_acttab[NA*6];
__device__ float    g_nonexist[BN*NC];
__device__ unsigned g_segmax[BN*NC];
__device__ float    g_invconst[NT];
__device__ int      g_bar1;   // producers (101) -> pair blocks
__device__ int      g_ctr2;   // pools+pairs (144) -> finalize
__device__ int      g_ctr3;   // finalize done (80) -> reset

__device__ __forceinline__ float warpsum(float v){
    #pragma unroll
    for(int o=16;o>0;o>>=1) v += __shfl_xor_sync(0xffffffffu, v, o);
    return v;
}
__device__ __forceinline__ unsigned fmap(float f){
    unsigned u=__float_as_uint(f);
    return (u & 0x80000000u) ? ~u : (u | 0x80000000u);
}
__device__ __forceinline__ float funmap(unsigned u){
    return __uint_as_float((u & 0x80000000u) ? (u ^ 0x80000000u) : ~u);
}
__device__ __forceinline__ float dot4(float4 a, float4 b){
    return a.x*b.x + a.y*b.y + a.z*b.z + a.w*b.w;
}

__global__ __launch_bounds__(TPB) void
kFused(const float* __restrict__ inp, const float* __restrict__ objmask,
       const float* __restrict__ W_obj, const float* __restrict__ b_obj,
       const float* __restrict__ W_act, const float* __restrict__ b_act,
       const float* __restrict__ W_tr,  const float* __restrict__ b_tr,
       const float* __restrict__ W_ne,  const float* __restrict__ b_ne,
       const float* __restrict__ obj_emb, const float* __restrict__ act_emb,
       const int* __restrict__ AA, const float* __restrict__ TR,
       const int* __restrict__ lookup, float* __restrict__ out){
    int blk = blockIdx.x;
    int tid = threadIdx.x, w = tid>>5, lane = tid&31;

    // ---------------- phase 1 ----------------
    if(blk < HEADB){
        // heads: 49 dots over one 512-dim row, latency-overlapped (<=4/warp)
        __shared__ float4 row[DD/4];
        __shared__ float  res[NO+NA];
        int bo = blk, b = bo/MO, o = bo%MO;
        const float4* ir = (const float4*)(inp + (size_t)bo*DD);
        if(tid < DD/4) row[tid]=ir[tid];
        __syncthreads();
        int nd=0; int cs[4]; const float4* Wp[4];
        for(int c=w; c<NDOT; c+=16){
            cs[nd]=c;
            if(c<NO)          Wp[nd] = (const float4*)(W_obj + (size_t)c*DD);
            else if(c<NO+NA)  Wp[nd] = (const float4*)(W_act + (size_t)(c-NO)*DD);
            else { int idx=c-NO-NA; int t=idx>>1, h=idx&1;
                   Wp[nd] = (const float4*)(W_tr + (size_t)t*FD + h*HF); }
            nd++;
        }
        float acc[4]={0.f,0.f,0.f,0.f};
        for(int d=lane; d<DD/4; d+=32){
            float4 r = row[d];
            #pragma unroll
            for(int s=0;s<4;s++) if(s<nd) acc[s] += dot4(r, Wp[s][d]);
        }
        #pragma unroll
        for(int s=0;s<4;s++) if(s<nd){
            float v = warpsum(acc[s]);
            if(lane==0){
                int c = cs[s];
                if(c<NO){ float x=v+b_obj[c]; res[c]=x; out[OFF_OBJ + bo*NO + c]=x; }
                else if(c<NO+NA){ float x=v+b_act[c-NO]; res[c]=x; out[OFF_ACT + bo*NA + (c-NO)]=x; }
                else __stcg(&g_inpdot[bo*6 + (c-NO-NA)], v);
            }
        }
        __syncthreads();
        if(tid==0){
            int best=0; float bv=res[0];
            #pragma unroll
            for(int c=1;c<NO;c++) if(res[c]>bv){ bv=res[c]; best=c; }
            __stcg(&g_objidx[bo], best);
        }
        if(w==0){
            bool s=false;
            if(lane < NA){
                int k = o*NA + lane;
                bool act_on = (res[NO+lane] > 0.0f) && (objmask[bo] == 1.0f);
                int  aa = AA[b*KK + k];
                s = act_on && (aa != -1);
                __stcg(&g_aaidx[b*KK+k], s ? aa : -1);
            }
            unsigned m = __ballot_sync(0xffffffffu, s);
            if(lane==0) __stcg(&g_sel6[bo], (int)(m & 0x3fu));
        }
    } else if(blk < HEADB + POOLB){
        int bb = blk - HEADB;
        int b = bb/PPB, part = bb%PPB;
        __shared__ float4 pooled[DD/4];
        __shared__ float  msum_s;
        if(w==0){
            float m = (lane<MO) ? objmask[b*MO+lane] : 0.f;
            m = warpsum(m);
            if(lane==0) msum_s = m;
        }
        __syncthreads();
        float invm = 1.0f/msum_s;
        if(tid < DD/4){
            float4 s = make_float4(0,0,0,0);
            #pragma unroll
            for(int o=0;o<MO;o++){
                float m = objmask[b*MO+o];
                float4 v = ((const float4*)(inp + ((size_t)b*MO+o)*DD))[tid];
                s.x += v.x*m; s.y += v.y*m; s.z += v.z*m; s.w += v.w*m;
            }
            pooled[tid] = make_float4(s.x*invm, s.y*invm, s.z*invm, s.w*invm);
        }
        __syncthreads();
        int c0 = part*38, c1 = c0+38; if(c1>NC) c1=NC;
        int nd=0; int cs[3]; const float4* Wp[3];
        for(int c=c0+w; c<c1; c+=16){ cs[nd]=c; Wp[nd]=(const float4*)(W_ne + (size_t)c*DD); nd++; }
        float acc[3]={0.f,0.f,0.f};
        for(int d=lane; d<DD/4; d+=32){
            float4 r = pooled[d];
            #pragma unroll
            for(int s=0;s<3;s++) if(s<nd) acc[s] += dot4(r, Wp[s][d]);
        }
        #pragma unroll
        for(int s=0;s<3;s++) if(s<nd){
            float v = warpsum(acc[s]);
            if(lane==0) __stcg(&g_nonexist[b*NC+cs[s]], v + b_ne[cs[s]]);
        }
    } else if(blk < HEADB + POOLB + TABB){
        int gw = (blk - HEADB - POOLB)*16 + w;      // 0..63
        for(int c=gw; c<NO*6 + NA*6 + NT; c+=64){
            if(c < NO*6 + NA*6){
                const float* src; const float* Wv;
                if(c < NO*6){
                    int oi=c/6, idx=c%6, t=idx>>1, h=idx&1;
                    src = obj_emb + (size_t)oi*EM;
                    Wv  = W_tr + (size_t)t*FD + h*HF + DD;
                } else {
                    int cc=c-NO*6; int a=cc/6, idx=cc%6, t=idx>>1, h=idx&1;
                    src = act_emb + (size_t)a*EM;
                    Wv  = W_tr + (size_t)t*FD + h*HF + DD + EM;
                }
                float4 a4 = ((const float4*)src)[lane];
                float4 b4 = ((const float4*)Wv)[lane];
                float acc = warpsum(dot4(a4,b4));
                if(lane==0){
                    if(c < NO*6) __stcg(&g_objtab[c], acc);
                    else         __stcg(&g_acttab[c-NO*6], acc);
                }
            } else {
                int t = c - NO*6 - NA*6;
                const float4* W = (const float4*)(W_tr + (size_t)t*FD);
                float acc=0.f;
                #pragma unroll
                for(int d=lane; d<FD/4; d+=32) acc += W[d].x+W[d].y+W[d].z+W[d].w;
                acc = warpsum(acc);
                if(lane==0) __stcg(&g_invconst[t], b_tr[t] - acc);
            }
        }
    } else {
        for(int i=tid; i<BN*NC; i+=TPB) __stcg(&g_segmax[i], 0u);
    }

    bool is_pool = (blk >= HEADB) && (blk < HEADB + POOLB);

    // producers signal pair blocks (pools are NOT needed until finalize)
    if(!is_pool){
        __threadfence();
        __syncthreads();
        if(tid==0) atomicAdd(&g_bar1, 1);
    } else {
        // pools signal finalize directly
        __threadfence();
        __syncthreads();
        if(tid==0) atomicAdd(&g_ctr2, 1);
        return;
    }

    if(blk >= PAIRB) return;   // non-pair producers are done

    // ---------------- pair blocks: wait for producers ----------------
    if(tid==0){ while(*((volatile int*)&g_bar1) < PRODB) { } }
    __syncthreads();
    __threadfence();

    // ---------------- phase 2: pairs ----------------
    {
        int b = blk / PCH, ch = blk % PCH;
        __shared__ float s1s[KK*NT], s2s[KK*NT], inv[NT], btr[NT];
        __shared__ int   aas[KK], sel6s[MO];
        __shared__ short cps[KK+1];
        __shared__ unsigned char sels[KK];

        if(tid < MO) sel6s[tid] = __ldcg(&g_sel6[b*MO+tid]);
        if(tid < KK){
            int k=tid, o=k/NA, a=k%NA;
            int oi = __ldcg(&g_objidx[b*MO+o]);
            aas[k] = __ldcg(&g_aaidx[b*KK+k]);
            #pragma unroll
            for(int t=0;t<NT;t++){
                s1s[k*NT+t] = __ldcg(&g_inpdot[(b*MO+o)*6 + t*2+0]) + __ldcg(&g_objtab[oi*6 + t*2+0]) + __ldcg(&g_acttab[a*6 + t*2+0]);
                s2s[k*NT+t] = __ldcg(&g_inpdot[(b*MO+o)*6 + t*2+1]) + __ldcg(&g_objtab[oi*6 + t*2+1]) + __ldcg(&g_acttab[a*6 + t*2+1]);
            }
        }
        if(tid < NT){ inv[tid]=__ldcg(&g_invconst[tid]); btr[tid]=b_tr[tid]; }
        __syncthreads();
        if(tid <= KK){
            int full = tid/NA, rem = tid%NA, c = 0;
            for(int o=0;o<full;o++) c += __popc(sel6s[o]);
            if(tid < KK) c += __popc(sel6s[full] & ((1<<rem)-1));
            cps[tid] = (short)c;
            if(tid < KK) sels[tid] = (unsigned char)((sel6s[full]>>rem) & 1);
        }
        __syncthreads();

        int p = ch*TPB + tid;
        if(p < PP){
            int S = cps[KK];
            int i = p/(KK-1), r = p - i*(KK-1);
            int j = (r<i) ? r : r+1;
            int si = sels[i];
            int vb = cps[i]*(S-1) + si*(cps[j] - (i<j ? 1 : 0));
            bool valid = si && sels[j];
            int q = valid ? vb : S*(S-1) + (p - vb);
            float* pl = out + OFF_PL + ((size_t)b*PP + q)*NT;
            float* tt = out + OFF_TT + ((size_t)b*PP + q)*NT;
            if(valid){
                const int*   lk  = lookup + ((size_t)aas[i]*NAA + aas[j])*NT;
                const float* trp = TR + (((size_t)b*KK + i)*KK + j)*NT;
                #pragma unroll
                for(int t=0;t<NT;t++){
                    float l = s1s[i*NT+t] + s2s[j*NT+t] + btr[t];
                    pl[t] = l;
                    tt[t] = trp[t];
                    atomicMax(&g_segmax[b*NC + lk[t]], fmap(l));
                }
            } else {
                #pragma unroll
                for(int t=0;t<NT;t++){ pl[t]=inv[t]; tt[t]=-1.0f; }
            }
        }
    }

    // ---------------- distributed finalize ----------------
    __threadfence();
    __syncthreads();
    if(tid==0){
        atomicAdd(&g_ctr2, 1);
        while(*((volatile int*)&g_ctr2) < DONEB) { }
    }
    __syncthreads();
    __threadfence();
    if(tid < FSL){
        int idx = blk*FSL + tid;
        unsigned u = __ldcg(&g_segmax[idx]);
        out[OFF_FINAL + idx] = u ? funmap(u) : __ldcg(&g_nonexist[idx]);
    }
    __syncthreads();
    if(tid==0){
        int old = atomicAdd(&g_ctr3, 1);
        if(old == PAIRB-1){
            // everyone is past all spins; reset for next graph replay
            *((volatile int*)&g_bar1) = 0;
            *((volatile int*)&g_ctr2) = 0;
            *((volatile int*)&g_ctr3) = 0;
        }
    }
}

extern "C" void kernel_launch(void* const* d_in, const int* in_sizes, int n_in,
                              void* d_out, int out_size){
    const float* inp     = (const float*)d_in[0];
    const float* objmask = (const float*)d_in[1];
    const float* TR      = (const float*)d_in[2];
    const float* W_obj   = (const float*)d_in[3];
    const float* b_obj   = (const float*)d_in[4];
    const float* W_act   = (const float*)d_in[5];
    const float* b_act   = (const float*)d_in[6];
    const float* W_tr    = (const float*)d_in[7];
    const float* b_tr    = (const float*)d_in[8];
    const float* W_ne    = (const float*)d_in[9];
    const float* b_ne    = (const float*)d_in[10];
    const float* obj_emb = (const float*)d_in[11];
    const float* act_emb = (const float*)d_in[12];
    const int*   AA      = (const int*)d_in[13];
    const int*   lookup  = (const int*)d_in[15];
    float* out = (float*)d_out;

    kFused<<<GRID, TPB>>>(inp, objmask, W_obj, b_obj, W_act, b_act,
                          W_tr, b_tr, W_ne, b_ne, obj_emb, act_emb,
                          AA, TR, lookup, out);
}